// round 6
// baseline (speedup 1.0000x reference)
#include <cuda_runtime.h>
#include <cuda_bf16.h>

// NearestMatcher: B rows, N=16 queries, T=8 targets.
//   tgt = (targets==0) ? 1e6 : targets
//   dist[n][t] = |pred_disp[n] - tgt[t]|;  cost_disp = min_t;  indices = argmin_t (first)
//   C = -sigmoid(pred_logits) + cost_disp
//   labels[i] = 1 iff C_i is the stable-minimum among queries with the same matched target
// (equivalent to the reference's argsort + sequential first-occurrence dedup)

#define NQ 16
#define NT 8
#define BIGV 1000000.0f

template<bool FULL>
__global__ __launch_bounds__(256)
void nearest_matcher_kernel(const float4* __restrict__ lg4,
                            const float4* __restrict__ pd4,
                            const float4* __restrict__ tg4,
                            float* __restrict__ out,
                            int B)
{
    int b = blockIdx.x * blockDim.x + threadIdx.x;
    if (b >= B) return;

    // ---- load targets [8] and apply null sentinel ----
    float tgt[NT];
    {
        float4 t0 = tg4[2 * b + 0];
        float4 t1 = tg4[2 * b + 1];
        tgt[0] = t0.x; tgt[1] = t0.y; tgt[2] = t0.z; tgt[3] = t0.w;
        tgt[4] = t1.x; tgt[5] = t1.y; tgt[6] = t1.z; tgt[7] = t1.w;
    }
#pragma unroll
    for (int t = 0; t < NT; t++)
        tgt[t] = (tgt[t] == 0.0f) ? BIGV : tgt[t];

    // ---- load pred_disp [16] and pred_logits [16] ----
    float pd[NQ], lg[NQ];
#pragma unroll
    for (int q = 0; q < 4; q++) {
        float4 v = pd4[4 * b + q];
        pd[4 * q + 0] = v.x; pd[4 * q + 1] = v.y;
        pd[4 * q + 2] = v.z; pd[4 * q + 3] = v.w;
        float4 w = lg4[4 * b + q];
        lg[4 * q + 0] = w.x; lg[4 * q + 1] = w.y;
        lg[4 * q + 2] = w.z; lg[4 * q + 3] = w.w;
    }

    // ---- per-query argmin over targets (strict < keeps FIRST index on ties,
    //      matching jnp.argmin), plus cost C ----
    float C[NQ];
    int   ind[NQ];
#pragma unroll
    for (int n = 0; n < NQ; n++) {
        float best = fabsf(pd[n] - tgt[0]);
        int   bi   = 0;
#pragma unroll
        for (int t = 1; t < NT; t++) {
            float d = fabsf(pd[n] - tgt[t]);
            if (d < best) { best = d; bi = t; }
        }
        // sigmoid; logits ~ N(0,1) so no overflow concerns
        float e = __expf(-lg[n]);
        float s = __fdividef(1.0f, 1.0f + e);
        C[n]   = best - s;
        ind[n] = bi;
    }

    if (FULL) {
        // ---- dedup: labels[i] = 1 iff i is the stable-min-C in its target group.
        // Pairwise i<j: if same group, the loser gets cleared. Ties (C equal)
        // clear j (the later index) == stable argsort behavior.
        unsigned lab = 0xFFFFu;
#pragma unroll
        for (int i = 0; i < NQ; i++) {
#pragma unroll
            for (int j = i + 1; j < NQ; j++) {
                if (ind[i] == ind[j]) {
                    if (C[j] < C[i]) lab &= ~(1u << i);
                    else             lab &= ~(1u << j);
                }
            }
        }

        // ---- write [ float(indices) | labels ] ----
        float4* oi = reinterpret_cast<float4*>(out) + 4 * (size_t)b;
#pragma unroll
        for (int q = 0; q < 4; q++) {
            oi[q] = make_float4((float)ind[4 * q + 0], (float)ind[4 * q + 1],
                                (float)ind[4 * q + 2], (float)ind[4 * q + 3]);
        }
        float4* ol = reinterpret_cast<float4*>(out + (size_t)B * NQ) + 4 * (size_t)b;
#pragma unroll
        for (int q = 0; q < 4; q++) {
            ol[q] = make_float4((lab >> (4 * q + 0)) & 1u ? 1.0f : 0.0f,
                                (lab >> (4 * q + 1)) & 1u ? 1.0f : 0.0f,
                                (lab >> (4 * q + 2)) & 1u ? 1.0f : 0.0f,
                                (lab >> (4 * q + 3)) & 1u ? 1.0f : 0.0f);
        }
    } else {
        // Fallback: indices-only output as int32
        int4* oi = reinterpret_cast<int4*>(out) + 4 * (size_t)b;
#pragma unroll
        for (int q = 0; q < 4; q++) {
            oi[q] = make_int4(ind[4 * q + 0], ind[4 * q + 1],
                              ind[4 * q + 2], ind[4 * q + 3]);
        }
    }
}

extern "C" void kernel_launch(void* const* d_in, const int* in_sizes, int n_in,
                              void* d_out, int out_size)
{
    // metadata order: pred_logits [B,16], pred_disp [B,16], targets [B,8]
    const float4* lg = reinterpret_cast<const float4*>(d_in[0]);
    const float4* pd = reinterpret_cast<const float4*>(d_in[1]);
    const float4* tg = reinterpret_cast<const float4*>(d_in[2]);
    int B = in_sizes[0] / NQ;

    const int threads = 256;
    const int blocks  = (B + threads - 1) / threads;

    if ((long long)out_size >= 2LL * B * NQ) {
        nearest_matcher_kernel<true><<<blocks, threads>>>(lg, pd, tg, (float*)d_out, B);
    } else {
        nearest_matcher_kernel<false><<<blocks, threads>>>(lg, pd, tg, (float*)d_out, B);
    }
}

// round 7
// speedup vs baseline: 1.5843x; 1.5843x over previous
#include <cuda_runtime.h>
#include <cuda_bf16.h>

// NearestMatcher: B rows, N=16 queries, T=8 targets.
//   tgt = (targets==0) ? 1e6 : targets
//   dist[n][t] = |pred_disp[n] - tgt[t]|;  cost_disp = min_t;  indices = argmin_t (first)
//   C = cost_disp - sigmoid(pred_logits)
//   labels[i] = 1 iff C_i is the stable-minimum among queries matched to the same target
// (== reference's argsort + sequential first-occurrence dedup)

#define NQ 16
#define NT 8
#define BIGV 1000000.0f

template<bool FULL>
__global__ __launch_bounds__(256, 4)
void nearest_matcher_kernel(const float4* __restrict__ lg4,
                            const float4* __restrict__ pd4,
                            const float4* __restrict__ tg4,
                            float* __restrict__ out,
                            int B)
{
    int b = blockIdx.x * blockDim.x + threadIdx.x;
    if (b >= B) return;

    // ---- front-load ALL global reads (8x LDG.128) for MLP ----
    float4 t0 = tg4[2 * b + 0];
    float4 t1 = tg4[2 * b + 1];
    float4 pv0 = pd4[4 * b + 0], pv1 = pd4[4 * b + 1],
           pv2 = pd4[4 * b + 2], pv3 = pd4[4 * b + 3];
    float4 lv0 = lg4[4 * b + 0], lv1 = lg4[4 * b + 1],
           lv2 = lg4[4 * b + 2], lv3 = lg4[4 * b + 3];

    float tgt[NT] = { t0.x, t0.y, t0.z, t0.w, t1.x, t1.y, t1.z, t1.w };
#pragma unroll
    for (int t = 0; t < NT; t++)
        tgt[t] = (tgt[t] == 0.0f) ? BIGV : tgt[t];

    float pd[NQ] = { pv0.x, pv0.y, pv0.z, pv0.w,  pv1.x, pv1.y, pv1.z, pv1.w,
                     pv2.x, pv2.y, pv2.z, pv2.w,  pv3.x, pv3.y, pv3.z, pv3.w };
    float lg[NQ] = { lv0.x, lv0.y, lv0.z, lv0.w,  lv1.x, lv1.y, lv1.z, lv1.w,
                     lv2.x, lv2.y, lv2.z, lv2.w,  lv3.x, lv3.y, lv3.z, lv3.w };

    // ---- per-query argmin over targets (strict < keeps FIRST index on ties,
    //      matching jnp.argmin). Index carried as FLOAT (exact for 0..7):
    //      no I2F later, and group-equality in dedup is a single float cmp. ----
    float C[NQ];
    float fi[NQ];
#pragma unroll
    for (int n = 0; n < NQ; n++) {
        float p    = pd[n];
        float best = fabsf(p - tgt[0]);
        float bi   = 0.0f;
#pragma unroll
        for (int t = 1; t < NT; t++) {
            float d = fabsf(p - tgt[t]);
            if (d < best) { best = d; bi = (float)t; }
        }
        // sigmoid; logits ~ N(0,1), no overflow concerns
        float s = __fdividef(1.0f, 1.0f + __expf(-lg[n]));
        C[n]  = best - s;
        fi[n] = bi;
    }

    if (FULL) {
        // ---- dedup: labels[i]=1 iff i is the stable-min-C within its target group.
        // Pairwise i<j: if same group, the loser is cleared; tie (C equal) clears j
        // (the later index) == stable argsort behavior. Four independent
        // accumulators break the 120-deep LOP dependency chain. ----
        unsigned labs[4] = { 0xFFFFu, 0xFFFFu, 0xFFFFu, 0xFFFFu };
#pragma unroll
        for (int i = 0; i < NQ; i++) {
#pragma unroll
            for (int j = i + 1; j < NQ; j++) {
                unsigned m = (C[j] < C[i]) ? (1u << i) : (1u << j);
                if (fi[i] == fi[j]) labs[j & 3] &= ~m;
            }
        }
        unsigned lab = labs[0] & labs[1] & labs[2] & labs[3];

        // ---- write [ float(indices) | labels ] ----
        float4* oi = reinterpret_cast<float4*>(out) + 4 * (size_t)b;
#pragma unroll
        for (int q = 0; q < 4; q++)
            oi[q] = make_float4(fi[4 * q + 0], fi[4 * q + 1],
                                fi[4 * q + 2], fi[4 * q + 3]);

        float lf[NQ];
#pragma unroll
        for (int n = 0; n < NQ; n++)
            lf[n] = (lab & (1u << n)) ? 1.0f : 0.0f;

        float4* ol = reinterpret_cast<float4*>(out + (size_t)B * NQ) + 4 * (size_t)b;
#pragma unroll
        for (int q = 0; q < 4; q++)
            ol[q] = make_float4(lf[4 * q + 0], lf[4 * q + 1],
                                lf[4 * q + 2], lf[4 * q + 3]);
    } else {
        // Fallback: indices-only output as int32
        int4* oi = reinterpret_cast<int4*>(out) + 4 * (size_t)b;
#pragma unroll
        for (int q = 0; q < 4; q++)
            oi[q] = make_int4((int)fi[4 * q + 0], (int)fi[4 * q + 1],
                              (int)fi[4 * q + 2], (int)fi[4 * q + 3]);
    }
}

extern "C" void kernel_launch(void* const* d_in, const int* in_sizes, int n_in,
                              void* d_out, int out_size)
{
    // metadata order: pred_logits [B,16], pred_disp [B,16], targets [B,8]
    const float4* lg = reinterpret_cast<const float4*>(d_in[0]);
    const float4* pd = reinterpret_cast<const float4*>(d_in[1]);
    const float4* tg = reinterpret_cast<const float4*>(d_in[2]);
    int B = in_sizes[0] / NQ;

    const int threads = 256;
    const int blocks  = (B + threads - 1) / threads;

    if ((long long)out_size >= 2LL * B * NQ) {
        nearest_matcher_kernel<true><<<blocks, threads>>>(lg, pd, tg, (float*)d_out, B);
    } else {
        nearest_matcher_kernel<false><<<blocks, threads>>>(lg, pd, tg, (float*)d_out, B);
    }
}

// round 8
// speedup vs baseline: 1.6301x; 1.0289x over previous
#include <cuda_runtime.h>
#include <cuda_bf16.h>

// NearestMatcher: B rows, N=16 queries, T=8 targets.
//   tgt = (targets==0) ? 1e6 : targets
//   dist[n][t] = |pred_disp[n] - tgt[t]|;  cost_disp = min_t;  indices = argmin_t (first)
//   C = cost_disp - sigmoid(pred_logits)
//   labels[i] = 1 iff C_i is the stable-minimum among queries matched to the same target
// (== reference's argsort + sequential first-occurrence dedup; strict-< everywhere
//  reproduces first-occurrence / stable tie-breaking exactly)

#define NQ 16
#define NT 8
#define BIGV 1000000.0f

template<bool FULL>
__global__ __launch_bounds__(128, 8)
void nearest_matcher_kernel(const float4* __restrict__ lg4,
                            const float4* __restrict__ pd4,
                            const float4* __restrict__ tg4,
                            float* __restrict__ out,
                            int B)
{
    int b = blockIdx.x * blockDim.x + threadIdx.x;
    if (b >= B) return;

    // ---- front-load ALL global reads (8x LDG.128) for MLP ----
    float4 t0 = tg4[2 * b + 0];
    float4 t1 = tg4[2 * b + 1];
    float4 pv0 = pd4[4 * b + 0], pv1 = pd4[4 * b + 1],
           pv2 = pd4[4 * b + 2], pv3 = pd4[4 * b + 3];
    float4 lv0 = lg4[4 * b + 0], lv1 = lg4[4 * b + 1],
           lv2 = lg4[4 * b + 2], lv3 = lg4[4 * b + 3];

    float tgt[NT] = { t0.x, t0.y, t0.z, t0.w, t1.x, t1.y, t1.z, t1.w };
#pragma unroll
    for (int t = 0; t < NT; t++)
        tgt[t] = (tgt[t] == 0.0f) ? BIGV : tgt[t];

    float pd[NQ] = { pv0.x, pv0.y, pv0.z, pv0.w,  pv1.x, pv1.y, pv1.z, pv1.w,
                     pv2.x, pv2.y, pv2.z, pv2.w,  pv3.x, pv3.y, pv3.z, pv3.w };
    float lg[NQ] = { lv0.x, lv0.y, lv0.z, lv0.w,  lv1.x, lv1.y, lv1.z, lv1.w,
                     lv2.x, lv2.y, lv2.z, lv2.w,  lv3.x, lv3.y, lv3.z, lv3.w };

    // ---- batch sigmoids first so MUFUs pipeline behind the argmin ALU work ----
    float sg[NQ];
#pragma unroll
    for (int n = 0; n < NQ; n++)
        sg[n] = __fdividef(1.0f, 1.0f + __expf(-lg[n]));

    // ---- per-query argmin over 8 targets, balanced tree (depth 3).
    // Value path: pure fminf (FMNMX, no predicate in the chain).
    // Index path: FSETP+FSEL beside it. Strict < keeps the LOWER original
    // index on exact ties at every level == jnp.argmin first-occurrence. ----
    float C[NQ];
    float fi[NQ];
#pragma unroll
    for (int n = 0; n < NQ; n++) {
        float p = pd[n];
        float d[NT];
#pragma unroll
        for (int t = 0; t < NT; t++)
            d[t] = fabsf(p - tgt[t]);

        // level 1: (0,1)(2,3)(4,5)(6,7)
        float m01 = fminf(d[0], d[1]);  float i01 = (d[1] < d[0]) ? 1.0f : 0.0f;
        float m23 = fminf(d[2], d[3]);  float i23 = (d[3] < d[2]) ? 3.0f : 2.0f;
        float m45 = fminf(d[4], d[5]);  float i45 = (d[5] < d[4]) ? 5.0f : 4.0f;
        float m67 = fminf(d[6], d[7]);  float i67 = (d[7] < d[6]) ? 7.0f : 6.0f;
        // level 2
        float m03 = fminf(m01, m23);    float i03 = (m23 < m01) ? i23 : i01;
        float m47 = fminf(m45, m67);    float i47 = (m67 < m45) ? i67 : i45;
        // level 3
        float m   = fminf(m03, m47);    fi[n] = (m47 < m03) ? i47 : i03;

        C[n] = m - sg[n];
    }

    if (FULL) {
        // ---- indices are final: store them NOW so the STGs overlap the dedup ----
        float4* oi = reinterpret_cast<float4*>(out) + 4 * (size_t)b;
#pragma unroll
        for (int q = 0; q < 4; q++)
            oi[q] = make_float4(fi[4 * q + 0], fi[4 * q + 1],
                                fi[4 * q + 2], fi[4 * q + 3]);

        // ---- dedup: labels[i]=1 iff i is the stable-min-C within its target group.
        // Pairwise i<j: loser cleared; tie (C equal) clears j (later index) ==
        // stable argsort. Four independent accumulators cap the LOP chain depth. ----
        unsigned labs0 = 0xFFFFu, labs1 = 0xFFFFu, labs2 = 0xFFFFu, labs3 = 0xFFFFu;
#pragma unroll
        for (int i = 0; i < NQ; i++) {
#pragma unroll
            for (int j = i + 1; j < NQ; j++) {
                bool eq = (fi[i] == fi[j]);
                unsigned m = (C[j] < C[i]) ? (1u << i) : (1u << j);
                unsigned clr = eq ? ~m : 0xFFFFFFFFu;
                switch (j & 3) {
                    case 0: labs0 &= clr; break;
                    case 1: labs1 &= clr; break;
                    case 2: labs2 &= clr; break;
                    default: labs3 &= clr; break;
                }
            }
        }
        unsigned lab = labs0 & labs1 & labs2 & labs3;

        float lf[NQ];
#pragma unroll
        for (int n = 0; n < NQ; n++)
            lf[n] = (lab & (1u << n)) ? 1.0f : 0.0f;

        float4* ol = reinterpret_cast<float4*>(out + (size_t)B * NQ) + 4 * (size_t)b;
#pragma unroll
        for (int q = 0; q < 4; q++)
            ol[q] = make_float4(lf[4 * q + 0], lf[4 * q + 1],
                                lf[4 * q + 2], lf[4 * q + 3]);
    } else {
        // Fallback: indices-only output as int32
        int4* oi = reinterpret_cast<int4*>(out) + 4 * (size_t)b;
#pragma unroll
        for (int q = 0; q < 4; q++)
            oi[q] = make_int4((int)fi[4 * q + 0], (int)fi[4 * q + 1],
                              (int)fi[4 * q + 2], (int)fi[4 * q + 3]);
    }
}

extern "C" void kernel_launch(void* const* d_in, const int* in_sizes, int n_in,
                              void* d_out, int out_size)
{
    // metadata order: pred_logits [B,16], pred_disp [B,16], targets [B,8]
    const float4* lg = reinterpret_cast<const float4*>(d_in[0]);
    const float4* pd = reinterpret_cast<const float4*>(d_in[1]);
    const float4* tg = reinterpret_cast<const float4*>(d_in[2]);
    int B = in_sizes[0] / NQ;

    const int threads = 128;
    const int blocks  = (B + threads - 1) / threads;

    if ((long long)out_size >= 2LL * B * NQ) {
        nearest_matcher_kernel<true><<<blocks, threads>>>(lg, pd, tg, (float*)d_out, B);
    } else {
        nearest_matcher_kernel<false><<<blocks, threads>>>(lg, pd, tg, (float*)d_out, B);
    }
}